// round 3
// baseline (speedup 1.0000x reference)
#include <cuda_runtime.h>

#define IMG_H 512
#define IMG_W 512

__constant__ float c_k[9];
__constant__ float c_w1[10];
__constant__ float c_b1[10];
__constant__ float c_w2[10];

// Full pointwise chain: gaussian -> MLP(1->10 relu ->1) -> sigmoid -> -0.5
__device__ __forceinline__ float act(float v) {
    float t = v - 1.0f;
    float g = __expf(-t * t);
    float s = 0.0f;
#pragma unroll
    for (int j = 0; j < 10; ++j) {
        float h = fmaf(c_w1[j], g, c_b1[j]);
        s = fmaf(c_w2[j], fmaxf(h, 0.0f), s);
    }
    float e = __expf(-s);
    float sig = __fdividef(1.0f, 1.0f + e);
    return sig - 0.5f;
}

// One NCA step. Each thread: 4 cols (float4) x T rows, sliding 3-row window.
// blockDim = (32, 8); grid.x = 4 so (blockIdx.x*32+tx)*4 spans all 512 columns.
template <int T>
__global__ __launch_bounds__(256) void step_kernel(const float* __restrict__ in,
                                                   float* __restrict__ out) {
    const int tx = threadIdx.x;                       // 0..31
    const int c0 = (blockIdx.x * 32 + tx) * 4;        // column of this thread's float4
    const int b  = blockIdx.z;
    const int y0 = (blockIdx.y * blockDim.y + threadIdx.y) * T;

    const float* img  = in  + (size_t)b * (IMG_H * IMG_W);
    float*       oimg = out + (size_t)b * (IMG_H * IMG_W);

    float win[3][6];   // 3-row sliding window, 6 cols: [c0-1, c0..c0+3, c0+4]

    auto load_row = [&](int y, float* r) {
#pragma unroll
        for (int i = 0; i < 6; ++i) r[i] = 0.0f;
        if (y >= 0 && y < IMG_H) {
            const float* p = img + y * IMG_W + c0;
            float4 v = *reinterpret_cast<const float4*>(p);
            r[1] = v.x; r[2] = v.y; r[3] = v.z; r[4] = v.w;
            if (c0 > 0)           r[0] = __ldg(p - 1);
            if (c0 + 4 < IMG_W)   r[5] = __ldg(p + 4);
        }
    };

    load_row(y0 - 1, win[0]);
    load_row(y0,     win[1]);

#pragma unroll
    for (int t = 0; t < T; ++t) {
        const int y = y0 + t;
        float* rm = win[(t + 0) % 3];   // row y-1
        float* rc = win[(t + 1) % 3];   // row y
        float* rp = win[(t + 2) % 3];   // row y+1
        load_row(y + 1, rp);

        float res[4];
#pragma unroll
        for (int i = 0; i < 4; ++i) {
            float v;
            v = c_k[0] * rm[i];
            v = fmaf(c_k[1], rm[i + 1], v);
            v = fmaf(c_k[2], rm[i + 2], v);
            v = fmaf(c_k[3], rc[i],     v);
            v = fmaf(c_k[4], rc[i + 1], v);
            v = fmaf(c_k[5], rc[i + 2], v);
            v = fmaf(c_k[6], rp[i],     v);
            v = fmaf(c_k[7], rp[i + 1], v);
            v = fmaf(c_k[8], rp[i + 2], v);
            res[i] = rc[i + 1] + act(v);   // residual update
        }
        float4 o;
        o.x = res[0]; o.y = res[1]; o.z = res[2]; o.w = res[3];
        *reinterpret_cast<float4*>(oimg + y * IMG_W + c0) = o;
    }
}

extern "C" void kernel_launch(void* const* d_in, const int* in_sizes, int n_in,
                              void* d_out, int out_size) {
    const float* x  = (const float*)d_in[0];
    const float* k  = (const float*)d_in[1];
    const float* w1 = (const float*)d_in[2];
    const float* b1 = (const float*)d_in[3];
    const float* w2 = (const float*)d_in[4];
    float* out = (float*)d_out;

    const int npix  = in_sizes[0];                 // B*1*H*W
    const int B     = npix / (IMG_H * IMG_W);
    const int steps = out_size / npix - 1;         // can't read device scalar under capture

    // Weights -> constant memory (device-to-device async copies: capturable)
    cudaMemcpyToSymbolAsync(c_k,  k,  9 * sizeof(float), 0, cudaMemcpyDeviceToDevice, 0);
    cudaMemcpyToSymbolAsync(c_w1, w1, 10 * sizeof(float), 0, cudaMemcpyDeviceToDevice, 0);
    cudaMemcpyToSymbolAsync(c_b1, b1, 10 * sizeof(float), 0, cudaMemcpyDeviceToDevice, 0);
    cudaMemcpyToSymbolAsync(c_w2, w2, 10 * sizeof(float), 0, cudaMemcpyDeviceToDevice, 0);

    // Slice 0 of the output is the initial state
    cudaMemcpyAsync(out, x, (size_t)npix * sizeof(float), cudaMemcpyDeviceToDevice, 0);

    constexpr int T = 4;
    dim3 blk(32, 8, 1);
    dim3 grd(IMG_W / (32 * 4), IMG_H / (8 * T), B);   // (4, 16, B)

    for (int s = 0; s < steps; ++s) {
        const float* src = out + (size_t)s       * npix;
        float*       dst = out + (size_t)(s + 1) * npix;
        step_kernel<T><<<grd, blk>>>(src, dst);
    }
}